// round 3
// baseline (speedup 1.0000x reference)
#include <cuda_runtime.h>

// ----------------------------------------------------------------------------
// MultiHeadSelfAttention: B=2, S=2048, D_MODEL=1024, H=16, depth=64, fp32.
//   1) fused QKV projection GEMM (blockIdx.z selects Q/K/V)
//   2) flash-style attention per (head, q-tile), online softmax
//   3) output projection GEMM
// All fp32 FFMA for a bit-trustworthy baseline (rel_err ~1e-6).
// ----------------------------------------------------------------------------

#define D_MODEL   1024
#define NUM_HEADS 16
#define DEPTH     64
#define BATCH     2
#define SEQ       2048
#define M_TOK     (BATCH * SEQ)   // 4096 token rows

// Scratch: __device__ globals (no allocation allowed anywhere).
__device__ float g_q[M_TOK * D_MODEL];
__device__ float g_k[M_TOK * D_MODEL];
__device__ float g_v[M_TOK * D_MODEL];
__device__ float g_attn[M_TOK * D_MODEL];

// ======================= SGEMM: C = A @ W + bias ============================
// A: [M, 1024] row-major, W: [1024, 1024] row-major, C: [M, 1024].
// 128x128 block tile, BK=16, 256 threads, 8x8 per-thread microtile.

#define BM 128
#define BN 128
#define BK 16
#define TM 8
#define TN 8

__device__ __forceinline__ void sgemm_body(
    const float* __restrict__ A,
    const float* __restrict__ W,
    const float* __restrict__ bias,
    float* __restrict__ C,
    float (*As)[BM], float (*Bs)[BN])
{
    const int K = D_MODEL;
    const int N = D_MODEL;
    const int tid = threadIdx.x;
    const int tx  = tid & 15;
    const int ty  = tid >> 4;
    const int brow = blockIdx.y;
    const int bcol = blockIdx.x;

    float acc[TM][TN];
    #pragma unroll
    for (int i = 0; i < TM; i++)
        #pragma unroll
        for (int j = 0; j < TN; j++) acc[i][j] = 0.0f;

    // A tile loaders: 128x16 = 512 float4, 2 per thread
    const int aRow = tid >> 2;          // 0..63 (and +64)
    const int aCol = (tid & 3) << 2;    // 0,4,8,12
    // B tile loaders: 16x128 = 512 float4, 2 per thread
    const int bRow = tid >> 5;          // 0..7 (and +8)
    const int bCol = (tid & 31) << 2;   // 0..124

    const float* Aptr = A + (size_t)(brow * BM) * K;
    const float* Wptr = W + bcol * BN;

    for (int k0 = 0; k0 < K; k0 += BK) {
        #pragma unroll
        for (int i = 0; i < 2; i++) {
            int r = aRow + i * 64;
            float4 v = *(const float4*)(Aptr + (size_t)r * K + k0 + aCol);
            As[aCol + 0][r] = v.x;
            As[aCol + 1][r] = v.y;
            As[aCol + 2][r] = v.z;
            As[aCol + 3][r] = v.w;
        }
        #pragma unroll
        for (int i = 0; i < 2; i++) {
            int r = bRow + i * 8;
            *(float4*)(&Bs[r][bCol]) =
                *(const float4*)(Wptr + (size_t)(k0 + r) * N + bCol);
        }
        __syncthreads();

        #pragma unroll
        for (int kk = 0; kk < BK; kk++) {
            float a[TM], b[TN];
            *(float4*)&a[0] = *(float4*)&As[kk][ty * TM];
            *(float4*)&a[4] = *(float4*)&As[kk][ty * TM + 4];
            *(float4*)&b[0] = *(float4*)&Bs[kk][tx * TN];
            *(float4*)&b[4] = *(float4*)&Bs[kk][tx * TN + 4];
            #pragma unroll
            for (int i = 0; i < TM; i++)
                #pragma unroll
                for (int j = 0; j < TN; j++)
                    acc[i][j] = fmaf(a[i], b[j], acc[i][j]);
        }
        __syncthreads();
    }

    #pragma unroll
    for (int i = 0; i < TM; i++) {
        int r = brow * BM + ty * TM + i;
        #pragma unroll
        for (int j = 0; j < TN; j += 4) {
            int c = bcol * BN + tx * TN + j;
            float4 o;
            o.x = acc[i][j + 0] + bias[c + 0];
            o.y = acc[i][j + 1] + bias[c + 1];
            o.z = acc[i][j + 2] + bias[c + 2];
            o.w = acc[i][j + 3] + bias[c + 3];
            *(float4*)(C + (size_t)r * N + c) = o;
        }
    }
}

__global__ __launch_bounds__(256, 2)
void qkv_kernel(const float* __restrict__ X,
                const float* __restrict__ wq, const float* __restrict__ bq,
                const float* __restrict__ wk, const float* __restrict__ bk,
                const float* __restrict__ wv, const float* __restrict__ bv)
{
    __shared__ float As[BK][BM];
    __shared__ float Bs[BK][BN];
    const float* W; const float* bias; float* C;
    if (blockIdx.z == 0)      { W = wq; bias = bq; C = g_q; }
    else if (blockIdx.z == 1) { W = wk; bias = bk; C = g_k; }
    else                      { W = wv; bias = bv; C = g_v; }
    sgemm_body(X, W, bias, C, As, Bs);
}

__global__ __launch_bounds__(256, 2)
void out_proj_kernel(const float* __restrict__ wo,
                     const float* __restrict__ bo,
                     float* __restrict__ out)
{
    __shared__ float As[BK][BM];
    __shared__ float Bs[BK][BN];
    sgemm_body(g_attn, wo, bo, out, As, Bs);
}

// ============================ Flash attention ===============================
// grid = (32 q-tiles, 32 b*h). Block 256 threads (16x16), 4x4 microtile on a
// 64x64 S tile. Q/K/V read from [token, 1024] layout at column h*64.
// K stored transposed in smem ([d][j]) so the S-loop loads are float4;
// KsT buffer is reused for P after the S phase.

#define BR   64
#define BC   64
#define SPAD 68   // 64 + 4 pad: keeps rows 16B-aligned, breaks bank alias

#define FLASH_SMEM (3 * BR * SPAD * 4)   // 52224 bytes

__global__ __launch_bounds__(256, 2)
void flash_kernel()
{
    extern __shared__ float sm[];
    float* Qs  = sm;                   // [64][SPAD]  (row i = q token, col d)
    float* KPs = sm + BR * SPAD;       // K^T [d][j], reused as P [i][j]
    float* Vs  = sm + 2 * BR * SPAD;   // [j][SPAD]   (row j = kv token, col d)

    const int tid = threadIdx.x;
    const int tx  = tid & 15;
    const int ty  = tid >> 4;
    const int qt  = blockIdx.x;        // 0..31
    const int bh  = blockIdx.y;        // 0..31
    const int b   = bh >> 4;
    const int h   = bh & 15;

    const size_t base = (size_t)b * SEQ * D_MODEL + (size_t)h * DEPTH;
    const float* Qg = g_q    + base;
    const float* Kg = g_k    + base;
    const float* Vg = g_v    + base;
    float*       Og = g_attn + base;

    const float scale = 0.125f;        // 1/sqrt(64)

    // Load Q tile (scaled). 64x64 floats = 1024 float4, 4 per thread.
    #pragma unroll
    for (int it = 0; it < 4; it++) {
        int f  = it * 256 + tid;
        int r  = f >> 4;               // 0..63
        int c4 = (f & 15) << 2;        // 0..60
        float4 v = *(const float4*)(Qg + (size_t)(qt * BR + r) * D_MODEL + c4);
        float* dst = &Qs[r * SPAD + c4];
        dst[0] = v.x * scale; dst[1] = v.y * scale;
        dst[2] = v.z * scale; dst[3] = v.w * scale;
    }

    float m[4], l[4], acc[4][4];
    #pragma unroll
    for (int i = 0; i < 4; i++) {
        m[i] = -1e30f;
        l[i] = 0.0f;
        #pragma unroll
        for (int j = 0; j < 4; j++) acc[i][j] = 0.0f;
    }

    for (int kt = 0; kt < SEQ / BC; kt++) {
        __syncthreads();   // protect Qs (first iter) and KPs/Vs reuse

        // Load K (transposed into KPs) and V.
        #pragma unroll
        for (int it = 0; it < 4; it++) {
            int f  = it * 256 + tid;
            int r  = f >> 4;
            int c4 = (f & 15) << 2;
            float4 kv = *(const float4*)(Kg + (size_t)(kt * BC + r) * D_MODEL + c4);
            KPs[(c4 + 0) * SPAD + r] = kv.x;
            KPs[(c4 + 1) * SPAD + r] = kv.y;
            KPs[(c4 + 2) * SPAD + r] = kv.z;
            KPs[(c4 + 3) * SPAD + r] = kv.w;
            float4 vv = *(const float4*)(Vg + (size_t)(kt * BC + r) * D_MODEL + c4);
            *(float4*)&Vs[r * SPAD + c4] = vv;
        }
        __syncthreads();

        // S[4][4] = (Q*scale) @ K^T for this thread's 4 rows x 4 cols.
        float s[4][4];
        #pragma unroll
        for (int i = 0; i < 4; i++)
            #pragma unroll
            for (int j = 0; j < 4; j++) s[i][j] = 0.0f;

        #pragma unroll
        for (int d0 = 0; d0 < DEPTH; d0 += 4) {
            float qa[4][4];
            #pragma unroll
            for (int ii = 0; ii < 4; ii++)
                *(float4*)qa[ii] = *(float4*)&Qs[(ty * 4 + ii) * SPAD + d0];
            #pragma unroll
            for (int dd = 0; dd < 4; dd++) {
                float kb[4];
                *(float4*)kb = *(float4*)&KPs[(d0 + dd) * SPAD + tx * 4];
                #pragma unroll
                for (int ii = 0; ii < 4; ii++)
                    #pragma unroll
                    for (int jj = 0; jj < 4; jj++)
                        s[ii][jj] = fmaf(qa[ii][dd], kb[jj], s[ii][jj]);
            }
        }

        // Online softmax update (per row; rows split across tx -> shfl reduce
        // within the 16-lane half-warp that shares ty).
        #pragma unroll
        for (int ii = 0; ii < 4; ii++) {
            float mx = fmaxf(fmaxf(s[ii][0], s[ii][1]), fmaxf(s[ii][2], s[ii][3]));
            #pragma unroll
            for (int off = 8; off > 0; off >>= 1)
                mx = fmaxf(mx, __shfl_xor_sync(0xffffffffu, mx, off));
            float mn = fmaxf(m[ii], mx);
            float alpha = __expf(m[ii] - mn);
            m[ii] = mn;
            float ps = 0.0f;
            #pragma unroll
            for (int jj = 0; jj < 4; jj++) {
                float p = __expf(s[ii][jj] - mn);
                s[ii][jj] = p;
                ps += p;
            }
            #pragma unroll
            for (int off = 8; off > 0; off >>= 1)
                ps += __shfl_xor_sync(0xffffffffu, ps, off);
            l[ii] = l[ii] * alpha + ps;
            #pragma unroll
            for (int jj = 0; jj < 4; jj++) acc[ii][jj] *= alpha;
        }

        __syncthreads();   // all threads done reading KPs as K^T
        #pragma unroll
        for (int ii = 0; ii < 4; ii++) {
            float4 pv = make_float4(s[ii][0], s[ii][1], s[ii][2], s[ii][3]);
            *(float4*)&KPs[(ty * 4 + ii) * SPAD + tx * 4] = pv;
        }
        __syncthreads();

        // acc += P @ V
        #pragma unroll
        for (int j0 = 0; j0 < BC; j0 += 4) {
            float pa[4][4];
            #pragma unroll
            for (int ii = 0; ii < 4; ii++)
                *(float4*)pa[ii] = *(float4*)&KPs[(ty * 4 + ii) * SPAD + j0];
            #pragma unroll
            for (int jj = 0; jj < 4; jj++) {
                float vb[4];
                *(float4*)vb = *(float4*)&Vs[(j0 + jj) * SPAD + tx * 4];
                #pragma unroll
                for (int ii = 0; ii < 4; ii++)
                    #pragma unroll
                    for (int dc = 0; dc < 4; dc++)
                        acc[ii][dc] = fmaf(pa[ii][jj], vb[dc], acc[ii][dc]);
            }
        }
    }

    // Normalize and write out: row qt*64 + 4ty+ii, cols h*64 + 4tx..4tx+3.
    #pragma unroll
    for (int ii = 0; ii < 4; ii++) {
        float inv = 1.0f / l[ii];
        float4 o = make_float4(acc[ii][0] * inv, acc[ii][1] * inv,
                               acc[ii][2] * inv, acc[ii][3] * inv);
        *(float4*)(Og + (size_t)(qt * BR + ty * 4 + ii) * D_MODEL + tx * 4) = o;
    }
}

// ============================== launch ======================================

extern "C" void kernel_launch(void* const* d_in, const int* in_sizes, int n_in,
                              void* d_out, int out_size)
{
    const float* X  = (const float*)d_in[0];
    const float* wq = (const float*)d_in[1];
    const float* bq = (const float*)d_in[2];
    const float* wk = (const float*)d_in[3];
    const float* bk = (const float*)d_in[4];
    const float* wv = (const float*)d_in[5];
    const float* bv = (const float*)d_in[6];
    const float* wo = (const float*)d_in[7];
    const float* bo = (const float*)d_in[8];
    float* out = (float*)d_out;
    (void)in_sizes; (void)n_in; (void)out_size;

    // Host-side attribute set (not a stream op; capture-safe, idempotent).
    cudaFuncSetAttribute(flash_kernel,
                         cudaFuncAttributeMaxDynamicSharedMemorySize,
                         FLASH_SMEM);

    dim3 gproj(D_MODEL / BN, M_TOK / BM, 3);   // 8 x 32 x 3
    qkv_kernel<<<gproj, 256>>>(X, wq, bq, wk, bk, wv, bv);

    dim3 gflash(SEQ / BR, BATCH * NUM_HEADS);  // 32 x 32
    flash_kernel<<<gflash, 256, FLASH_SMEM>>>();

    dim3 gout(D_MODEL / BN, M_TOK / BM);       // 8 x 32
    out_proj_kernel<<<gout, 256>>>(wo, bo, out);
}

// round 7
// speedup vs baseline: 1.0522x; 1.0522x over previous
#include <cuda_runtime.h>

// ----------------------------------------------------------------------------
// MultiHeadSelfAttention: B=2, S=2048, D_MODEL=1024, H=16, depth=64, fp32.
//   1) fused QKV projection GEMM (blockIdx.z selects Q/K/V)
//   2) flash-style attention per (head, q-tile), online softmax
//   3) output projection GEMM
// Round 3: all FMA inner loops use packed fma.rn.f32x2 (FFMA2, 2 MACs/issue).
// Flash keeps K row-major (no smem transpose) and pairs the S-phase along d.
// ----------------------------------------------------------------------------

#define D_MODEL   1024
#define NUM_HEADS 16
#define DEPTH     64
#define BATCH     2
#define SEQ       2048
#define M_TOK     (BATCH * SEQ)   // 4096 token rows

typedef unsigned long long u64;

__device__ __forceinline__ u64 pack_dup(float x) {
    u64 r; asm("mov.b64 %0, {%1, %1};" : "=l"(r) : "f"(x)); return r;
}
__device__ __forceinline__ void ffma2(u64 &d, u64 a, u64 b) {
    asm("fma.rn.f32x2 %0, %1, %2, %0;" : "+l"(d) : "l"(a), "l"(b));
}
__device__ __forceinline__ void fmul2(u64 &d, u64 a) {
    asm("mul.rn.f32x2 %0, %0, %1;" : "+l"(d) : "l"(a));
}
__device__ __forceinline__ float2 unpack2(u64 v) {
    float2 r; asm("mov.b64 {%0, %1}, %2;" : "=f"(r.x), "=f"(r.y) : "l"(v));
    return r;
}

// Scratch: __device__ globals (no allocation allowed anywhere).
__device__ float g_q[M_TOK * D_MODEL];
__device__ float g_k[M_TOK * D_MODEL];
__device__ float g_v[M_TOK * D_MODEL];
__device__ float g_attn[M_TOK * D_MODEL];

// ======================= SGEMM: C = A @ W + bias ============================
// 128x128 block tile, BK=16, 256 threads, 8x8 per-thread microtile, FFMA2.

#define BM 128
#define BN 128
#define BK 16
#define TM 8
#define TN 8

__device__ __forceinline__ void sgemm_body(
    const float* __restrict__ A,
    const float* __restrict__ W,
    const float* __restrict__ bias,
    float* __restrict__ C,
    float (*As)[BM], float (*Bs)[BN])
{
    const int K = D_MODEL;
    const int N = D_MODEL;
    const int tid = threadIdx.x;
    const int tx  = tid & 15;
    const int ty  = tid >> 4;
    const int brow = blockIdx.y;
    const int bcol = blockIdx.x;

    // Accumulators as packed f32x2 pairs along N: acc2[i][j] = (c[2j], c[2j+1])
    u64 acc2[TM][TN / 2];
    #pragma unroll
    for (int i = 0; i < TM; i++)
        #pragma unroll
        for (int j = 0; j < TN / 2; j++) acc2[i][j] = 0ULL;

    // A tile loaders: 128x16 = 512 float4, 2 per thread
    const int aRow = tid >> 2;          // 0..63 (and +64)
    const int aCol = (tid & 3) << 2;    // 0,4,8,12
    // B tile loaders: 16x128 = 512 float4, 2 per thread
    const int bRow = tid >> 5;          // 0..7 (and +8)
    const int bCol = (tid & 31) << 2;   // 0..124

    const float* Aptr = A + (size_t)(brow * BM) * K;
    const float* Wptr = W + bcol * BN;

    for (int k0 = 0; k0 < K; k0 += BK) {
        #pragma unroll
        for (int i = 0; i < 2; i++) {
            int r = aRow + i * 64;
            float4 v = *(const float4*)(Aptr + (size_t)r * K + k0 + aCol);
            As[aCol + 0][r] = v.x;
            As[aCol + 1][r] = v.y;
            As[aCol + 2][r] = v.z;
            As[aCol + 3][r] = v.w;
        }
        #pragma unroll
        for (int i = 0; i < 2; i++) {
            int r = bRow + i * 8;
            *(float4*)(&Bs[r][bCol]) =
                *(const float4*)(Wptr + (size_t)(k0 + r) * N + bCol);
        }
        __syncthreads();

        #pragma unroll
        for (int kk = 0; kk < BK; kk++) {
            float a[TM];
            *(float4*)&a[0] = *(const float4*)&As[kk][ty * TM];
            *(float4*)&a[4] = *(const float4*)&As[kk][ty * TM + 4];
            ulonglong2 b01 = *(const ulonglong2*)&Bs[kk][tx * TN];
            ulonglong2 b23 = *(const ulonglong2*)&Bs[kk][tx * TN + 4];
            u64 bp[4];
            bp[0] = b01.x; bp[1] = b01.y; bp[2] = b23.x; bp[3] = b23.y;
            u64 ap[TM];
            #pragma unroll
            for (int i = 0; i < TM; i++) ap[i] = pack_dup(a[i]);
            #pragma unroll
            for (int i = 0; i < TM; i++)
                #pragma unroll
                for (int j = 0; j < TN / 2; j++)
                    ffma2(acc2[i][j], ap[i], bp[j]);
        }
        __syncthreads();
    }

    #pragma unroll
    for (int i = 0; i < TM; i++) {
        int r = brow * BM + ty * TM + i;
        #pragma unroll
        for (int j = 0; j < TN; j += 4) {
            int c = bcol * BN + tx * TN + j;
            float2 p0 = unpack2(acc2[i][j / 2]);
            float2 p1 = unpack2(acc2[i][j / 2 + 1]);
            float4 o;
            o.x = p0.x + bias[c + 0];
            o.y = p0.y + bias[c + 1];
            o.z = p1.x + bias[c + 2];
            o.w = p1.y + bias[c + 3];
            *(float4*)(C + (size_t)r * N + c) = o;
        }
    }
}

__global__ __launch_bounds__(256, 2)
void qkv_kernel(const float* __restrict__ X,
                const float* __restrict__ wq, const float* __restrict__ bq,
                const float* __restrict__ wk, const float* __restrict__ bk,
                const float* __restrict__ wv, const float* __restrict__ bv)
{
    __shared__ float As[BK][BM];
    __shared__ float Bs[BK][BN];
    const float* W; const float* bias; float* C;
    if (blockIdx.z == 0)      { W = wq; bias = bq; C = g_q; }
    else if (blockIdx.z == 1) { W = wk; bias = bk; C = g_k; }
    else                      { W = wv; bias = bv; C = g_v; }
    sgemm_body(X, W, bias, C, As, Bs);
}

__global__ __launch_bounds__(256, 2)
void out_proj_kernel(const float* __restrict__ wo,
                     const float* __restrict__ bo,
                     float* __restrict__ out)
{
    __shared__ float As[BK][BM];
    __shared__ float Bs[BK][BN];
    sgemm_body(g_attn, wo, bo, out, As, Bs);
}

// ============================ Flash attention ===============================
// grid = (32 q-tiles, 32 b*h). Block 256 threads (16x16), 4x4 microtile on a
// 64x64 S tile. Q/K/V all row-major in smem ([token][d], stride SPAD).
// Thread (tx,ty) owns S rows ty*4+ii and strided columns j = tx + 16*jj,
// so S-phase K reads are per-row float4s at the crossbar floor, and both
// operand pairs for fma.f32x2 come free from float4 loads (pair along d).
// Ks buffer is reused to hold P between the S and PV phases.

#define BR   64
#define BC   64
#define SPAD 68   // 64 + 4 pad: keeps rows 16B-aligned, breaks bank alias

#define FLASH_SMEM (3 * BR * SPAD * 4)   // 52224 bytes

__global__ __launch_bounds__(256, 2)
void flash_kernel()
{
    extern __shared__ float sm[];
    float* Qs = sm;                    // [64][SPAD]  (row i = q token, col d)
    float* Ks = sm + BR * SPAD;        // [64][SPAD]  (row j = kv token), -> P
    float* Vs = sm + 2 * BR * SPAD;    // [64][SPAD]

    const int tid = threadIdx.x;
    const int tx  = tid & 15;
    const int ty  = tid >> 4;
    const int qt  = blockIdx.x;        // 0..31
    const int bh  = blockIdx.y;        // 0..31
    const int b   = bh >> 4;
    const int h   = bh & 15;

    const size_t base = (size_t)b * SEQ * D_MODEL + (size_t)h * DEPTH;
    const float* Qg = g_q    + base;
    const float* Kg = g_k    + base;
    const float* Vg = g_v    + base;
    float*       Og = g_attn + base;

    const float scale = 0.125f;        // 1/sqrt(64)

    // Load Q tile (scaled). 64x64 floats = 1024 float4, 4 per thread.
    #pragma unroll
    for (int it = 0; it < 4; it++) {
        int f  = it * 256 + tid;
        int r  = f >> 4;               // 0..63
        int c4 = (f & 15) << 2;        // 0..60
        float4 v = *(const float4*)(Qg + (size_t)(qt * BR + r) * D_MODEL + c4);
        float* dst = &Qs[r * SPAD + c4];
        dst[0] = v.x * scale; dst[1] = v.y * scale;
        dst[2] = v.z * scale; dst[3] = v.w * scale;
    }

    float m[4], l[4];
    u64 acc2[4][2];                    // packed pairs along depth (tx*4 .. +3)
    #pragma unroll
    for (int i = 0; i < 4; i++) {
        m[i] = -1e30f;
        l[i] = 0.0f;
        acc2[i][0] = 0ULL;
        acc2[i][1] = 0ULL;
    }

    for (int kt = 0; kt < SEQ / BC; kt++) {
        __syncthreads();   // protect Qs (first iter) and Ks(P)/Vs reuse

        // Load K and V row-major (same pattern as Q).
        #pragma unroll
        for (int it = 0; it < 4; it++) {
            int f  = it * 256 + tid;
            int r  = f >> 4;
            int c4 = (f & 15) << 2;
            *(float4*)&Ks[r * SPAD + c4] =
                *(const float4*)(Kg + (size_t)(kt * BC + r) * D_MODEL + c4);
            *(float4*)&Vs[r * SPAD + c4] =
                *(const float4*)(Vg + (size_t)(kt * BC + r) * D_MODEL + c4);
        }
        __syncthreads();

        // S-phase: s2 pairs accumulate along d (even/odd interleave);
        // thread covers rows ty*4+ii, cols tx+16*jj.
        u64 s2[4][4];
        #pragma unroll
        for (int i = 0; i < 4; i++)
            #pragma unroll
            for (int j = 0; j < 4; j++) s2[i][j] = 0ULL;

        #pragma unroll
        for (int d0 = 0; d0 < DEPTH; d0 += 4) {
            ulonglong2 qa2[4];
            #pragma unroll
            for (int ii = 0; ii < 4; ii++)
                qa2[ii] = *(const ulonglong2*)&Qs[(ty * 4 + ii) * SPAD + d0];
            #pragma unroll
            for (int jj = 0; jj < 4; jj++) {
                ulonglong2 kb =
                    *(const ulonglong2*)&Ks[(tx + 16 * jj) * SPAD + d0];
                #pragma unroll
                for (int ii = 0; ii < 4; ii++) {
                    ffma2(s2[ii][jj], qa2[ii].x, kb.x);
                    ffma2(s2[ii][jj], qa2[ii].y, kb.y);
                }
            }
        }

        // Horizontal fold pairs -> scalar scores.
        float s[4][4];
        #pragma unroll
        for (int ii = 0; ii < 4; ii++)
            #pragma unroll
            for (int jj = 0; jj < 4; jj++) {
                float2 t = unpack2(s2[ii][jj]);
                s[ii][jj] = t.x + t.y;
            }

        // Online softmax (row reduction over the 16 tx lanes sharing ty).
        #pragma unroll
        for (int ii = 0; ii < 4; ii++) {
            float mx = fmaxf(fmaxf(s[ii][0], s[ii][1]),
                             fmaxf(s[ii][2], s[ii][3]));
            #pragma unroll
            for (int off = 8; off > 0; off >>= 1)
                mx = fmaxf(mx, __shfl_xor_sync(0xffffffffu, mx, off));
            float mn = fmaxf(m[ii], mx);
            float alpha = __expf(m[ii] - mn);
            m[ii] = mn;
            float ps = 0.0f;
            #pragma unroll
            for (int jj = 0; jj < 4; jj++) {
                float p = __expf(s[ii][jj] - mn);
                s[ii][jj] = p;
                ps += p;
            }
            #pragma unroll
            for (int off = 8; off > 0; off >>= 1)
                ps += __shfl_xor_sync(0xffffffffu, ps, off);
            l[ii] = l[ii] * alpha + ps;
            u64 av = pack_dup(alpha);
            fmul2(acc2[ii][0], av);
            fmul2(acc2[ii][1], av);
        }

        __syncthreads();   // everyone done reading Ks -> reuse as P
        #pragma unroll
        for (int ii = 0; ii < 4; ii++)
            #pragma unroll
            for (int jj = 0; jj < 4; jj++)
                Ks[(ty * 4 + ii) * SPAD + tx + 16 * jj] = s[ii][jj];
        __syncthreads();

        // PV-phase: acc pairs along depth; V pairs free from float4 loads.
        #pragma unroll
        for (int j0 = 0; j0 < BC; j0 += 4) {
            float pa[4][4];
            #pragma unroll
            for (int ii = 0; ii < 4; ii++)
                *(float4*)pa[ii] =
                    *(const float4*)&Ks[(ty * 4 + ii) * SPAD + j0];
            #pragma unroll
            for (int jj = 0; jj < 4; jj++) {
                ulonglong2 vb =
                    *(const ulonglong2*)&Vs[(j0 + jj) * SPAD + tx * 4];
                #pragma unroll
                for (int ii = 0; ii < 4; ii++) {
                    u64 pp = pack_dup(pa[ii][jj]);
                    ffma2(acc2[ii][0], pp, vb.x);
                    ffma2(acc2[ii][1], pp, vb.y);
                }
            }
        }
    }

    // Normalize and write out: row qt*64 + 4ty+ii, cols h*64 + 4tx..4tx+3.
    #pragma unroll
    for (int ii = 0; ii < 4; ii++) {
        float inv = 1.0f / l[ii];
        float2 p0 = unpack2(acc2[ii][0]);
        float2 p1 = unpack2(acc2[ii][1]);
        float4 o = make_float4(p0.x * inv, p0.y * inv,
                               p1.x * inv, p1.y * inv);
        *(float4*)(Og + (size_t)(qt * BR + ty * 4 + ii) * D_MODEL + tx * 4) = o;
    }
}

// ============================== launch ======================================

extern "C" void kernel_launch(void* const* d_in, const int* in_sizes, int n_in,
                              void* d_out, int out_size)
{
    const float* X  = (const float*)d_in[0];
    const float* wq = (const float*)d_in[1];
    const float* bq = (const float*)d_in[2];
    const float* wk = (const float*)d_in[3];
    const float* bk = (const float*)d_in[4];
    const float* wv = (const float*)d_in[5];
    const float* bv = (const float*)d_in[6];
    const float* wo = (const float*)d_in[7];
    const float* bo = (const float*)d_in[8];
    float* out = (float*)d_out;
    (void)in_sizes; (void)n_in; (void)out_size;

    cudaFuncSetAttribute(flash_kernel,
                         cudaFuncAttributeMaxDynamicSharedMemorySize,
                         FLASH_SMEM);

    dim3 gproj(D_MODEL / BN, M_TOK / BM, 3);   // 8 x 32 x 3
    qkv_kernel<<<gproj, 256>>>(X, wq, bq, wk, bk, wv, bv);

    dim3 gflash(SEQ / BR, BATCH * NUM_HEADS);  // 32 x 32
    flash_kernel<<<gflash, 256, FLASH_SMEM>>>();

    dim3 gout(D_MODEL / BN, M_TOK / BM);       // 8 x 32
    out_proj_kernel<<<gout, 256>>>(wo, bo, out);
}